// round 1
// baseline (speedup 1.0000x reference)
#include <cuda_runtime.h>
#include <math.h>

#define M_   24
#define TS_  60
#define NX_  192
#define NY_  192
#define NG_  50
#define T_   50
#define HD_  32   // H*D
#define H_   4
#define D_   8

// Precomputed tables (kernel 1 -> kernel 2)
__device__ float g_w[M_];
__device__ int   g_off[T_][M_];      // (m*TS + ti[t][m]) * NX*NY
__device__ int   g_ixA[NG_];
__device__ float g_fxA[NG_];
__device__ float g_mxA[NG_];
__device__ int   g_iyA[M_][NG_];
__device__ float g_e0[M_][NG_];      // w[m] * my * (1-fy)
__device__ float g_e1[M_][NG_];      // w[m] * my * fy

// jnp.linspace(0,100,192): delta = 100/191 (f32), endpoint forced exact.
__device__ __forceinline__ float gridx(int k) {
    return (k == NX_ - 1) ? 100.0f : (float)k * (100.0f / 191.0f);
}

__global__ void setup_kernel(const float* __restrict__ params,
                             const float* __restrict__ src_y,
                             const float* __restrict__ stl,
                             const float* __restrict__ Wq,
                             const float* __restrict__ bq,
                             const float* __restrict__ Wk,
                             const float* __restrict__ bk,
                             const float* __restrict__ lyt_p,
                             const float* __restrict__ cut_p,
                             const float* __restrict__ nit_p)
{
    __shared__ float s_w[M_];
    __shared__ float s_scale[M_];
    const int tid = threadIdx.x;
    const float lyt = *lyt_p;

    if (tid == 0) {
        // --- attention + Gaussian weights, serial (tiny) ---
        float ly_n[M_], cu_n[M_], ni_n[M_];
        for (int m = 0; m < M_; m++) {
            float lys  = params[3*m + 0];
            ly_n[m] = (lys - 30.0f) / 90.0f;
            cu_n[m] = params[3*m + 1] / 0.0029f;
            ni_n[m] = params[3*m + 2] / 0.0018f;
            s_scale[m] = lyt / lys;
        }
        float t_ly = (lyt - 30.0f) / 90.0f;
        float t_cu = (*cut_p) / 0.0029f;
        float t_ni = (*nit_p) / 0.0018f;

        float Q[HD_];
        for (int k = 0; k < HD_; k++)
            Q[k] = t_ly*Wq[k] + t_cu*Wq[HD_ + k] + t_ni*Wq[2*HD_ + k] + bq[k];

        float logits[M_][H_];
        const float inv_sqrt_d = 1.0f / sqrtf((float)D_);
        for (int m = 0; m < M_; m++) {
            for (int h = 0; h < H_; h++) {
                float acc = 0.0f;
                for (int d = 0; d < D_; d++) {
                    int k = h*D_ + d;
                    float Kv = ly_n[m]*Wk[k] + cu_n[m]*Wk[HD_ + k] + ni_n[m]*Wk[2*HD_ + k] + bk[k];
                    acc += Kv * Q[k];
                }
                logits[m][h] = acc * inv_sqrt_d;
            }
        }
        // softmax over m per head, then mean over heads
        float attn[M_];
        for (int m = 0; m < M_; m++) attn[m] = 0.0f;
        for (int h = 0; h < H_; h++) {
            float mx = -1e30f;
            for (int m = 0; m < M_; m++) mx = fmaxf(mx, logits[m][h]);
            float s = 0.0f;
            for (int m = 0; m < M_; m++) s += expf(logits[m][h] - mx);
            for (int m = 0; m < M_; m++) attn[m] += expf(logits[m][h] - mx) / s;
        }
        float swv[M_];
        float ssum = 0.0f;
        for (int m = 0; m < M_; m++) {
            attn[m] *= (1.0f / (float)H_);
            float d2 = ((ly_n[m]-t_ly)*(ly_n[m]-t_ly) +
                        (cu_n[m]-t_cu)*(cu_n[m]-t_cu) +
                        (ni_n[m]-t_ni)*(ni_n[m]-t_ni)) / (0.2f * 0.2f);
            swv[m] = expf(-d2 * 0.5f);
            ssum += swv[m];
        }
        float wsum = 0.0f;
        for (int m = 0; m < M_; m++) {
            swv[m] /= (ssum + 1e-12f);
            swv[m] *= attn[m];
            wsum += swv[m];
        }
        for (int m = 0; m < M_; m++) {
            s_w[m] = swv[m] / (wsum + 1e-12f);
            g_w[m] = s_w[m];
        }
    }
    __syncthreads();

    // --- x-axis interp setup (uniform grids, searchsorted 'right' semantics) ---
    if (tid < NG_) {
        float q = (tid == NG_-1) ? 100.0f : (float)tid * (100.0f / 49.0f);
        int lo = 0, hi = NX_;
        while (lo < hi) { int mid = (lo + hi) >> 1; if (gridx(mid) <= q) lo = mid + 1; else hi = mid; }
        int idx = min(max(lo - 1, 0), NX_ - 2);
        float g0 = gridx(idx), g1 = gridx(idx + 1);
        g_ixA[tid] = idx;
        g_fxA[tid] = (q - g0) / (g1 - g0);
        g_mxA[tid] = (q >= 0.0f && q <= 100.0f) ? 1.0f : 0.0f;
    }

    // --- y-axis interp setup per (m, j), mask+weight folded ---
    for (int p = tid; p < M_ * NG_; p += blockDim.x) {
        int m = p / NG_, j = p % NG_;
        float q  = (float)j / 49.0f * lyt;
        float sc = s_scale[m];
        const float* ys = src_y + m * NY_;
        int lo = 0, hi = NY_;
        while (lo < hi) { int mid = (lo + hi) >> 1; if (ys[mid]*sc <= q) lo = mid + 1; else hi = mid; }
        int idx = min(max(lo - 1, 0), NY_ - 2);
        float gy0 = ys[idx] * sc, gy1 = ys[idx + 1] * sc;
        float fy = (q - gy0) / (gy1 - gy0);
        float inb = (q >= ys[0]*sc && q <= ys[NY_-1]*sc) ? 1.0f : 0.0f;
        float wm = s_w[m] * inb;
        g_iyA[m][j] = idx;
        g_e0[m][j]  = wm * (1.0f - fy);
        g_e1[m][j]  = wm * fy;
    }

    // --- time index -> slice offsets (round-half-even like jnp.round) ---
    for (int p = tid; p < T_ * M_; p += blockDim.x) {
        int t = p / M_, m = p % M_;
        float tv = (t == T_-1) ? 200.0f : (float)t * (200.0f / 49.0f);
        float r = rintf(tv / stl[m] * (float)(TS_ - 1));
        int ti = min(max((int)r, 0), TS_ - 1);
        g_off[t][m] = (m * TS_ + ti) * (NX_ * NY_);
    }
}

__global__ __launch_bounds__(256)
void interp_kernel(const float* __restrict__ c1,
                   const float* __restrict__ c2,
                   const float* __restrict__ cut_p,
                   const float* __restrict__ nit_p,
                   float* __restrict__ out)
{
    const int total = 2 * T_ * NG_ * NG_;
    int idx = blockIdx.x * blockDim.x + threadIdx.x;
    if (idx >= total) return;

    int j = idx % NG_;
    int i = (idx / NG_) % NG_;
    int t = (idx / (NG_ * NG_)) % T_;
    int f = idx / (T_ * NG_ * NG_);

    const float* __restrict__ base = f ? c2 : c1;
    const int   ix  = g_ixA[i];
    const float fx  = g_fxA[i];
    const float fx1 = 1.0f - fx;

    float acc = 0.0f;
#pragma unroll 6
    for (int m = 0; m < M_; m++) {
        const float* __restrict__ s = base + g_off[t][m] + ix * NY_;
        int iy = g_iyA[m][j];
        float v00 = __ldg(s + iy);
        float v01 = __ldg(s + iy + 1);
        float v10 = __ldg(s + NY_ + iy);
        float v11 = __ldg(s + NY_ + iy + 1);
        acc += (v00 * fx1 + v10 * fx) * g_e0[m][j]
             + (v01 * fx1 + v11 * fx) * g_e1[m][j];
    }
    float val = acc * g_mxA[i];
    if (f == 0 && j == 0)       val = *cut_p;
    if (f == 1 && j == NG_ - 1) val = *nit_p;
    out[idx] = val;
}

extern "C" void kernel_launch(void* const* d_in, const int* in_sizes, int n_in,
                              void* d_out, int out_size)
{
    const float* c1    = (const float*)d_in[0];
    const float* c2    = (const float*)d_in[1];
    const float* params= (const float*)d_in[2];
    const float* src_y = (const float*)d_in[3];
    const float* stl   = (const float*)d_in[4];
    const float* Wq    = (const float*)d_in[5];
    const float* bq    = (const float*)d_in[6];
    const float* Wk    = (const float*)d_in[7];
    const float* bk    = (const float*)d_in[8];
    const float* lyt   = (const float*)d_in[9];
    const float* cut   = (const float*)d_in[10];
    const float* nit   = (const float*)d_in[11];
    float* out = (float*)d_out;

    setup_kernel<<<1, 256>>>(params, src_y, stl, Wq, bq, Wk, bk, lyt, cut, nit);

    const int total = 2 * T_ * NG_ * NG_;
    interp_kernel<<<(total + 255) / 256, 256>>>(c1, c2, cut, nit, out);
}

// round 2
// speedup vs baseline: 1.1912x; 1.1912x over previous
#include <cuda_runtime.h>
#include <math.h>

#define M_   24
#define TS_  60
#define NX_  192
#define NY_  192
#define NG_  50
#define T_   50
#define HD_  32   // H*D
#define H_   4
#define D_   8

// Compacted tables (kernel 1 -> kernel 2); slot k = k-th significant member
__device__ int   g_mcnt;
__device__ int   g_off[T_][M_];      // (m*TS + ti[t][m]) * NX*NY, compact slots
__device__ int   g_ixA[NG_];
__device__ float g_fxA[NG_];
__device__ float g_mxA[NG_];
__device__ int   g_iyA[M_][NG_];
__device__ float g_e0[M_][NG_];      // w[m] * my * (1-fy)
__device__ float g_e1[M_][NG_];      // w[m] * my * fy

// jnp.linspace(0,100,192): delta = 100/191 (f32), endpoint forced exact.
__device__ __forceinline__ float gridx(int k) {
    return (k == NX_ - 1) ? 100.0f : (float)k * (100.0f / 191.0f);
}

__global__ void setup_kernel(const float* __restrict__ params,
                             const float* __restrict__ src_y,
                             const float* __restrict__ stl,
                             const float* __restrict__ Wq,
                             const float* __restrict__ bq,
                             const float* __restrict__ Wk,
                             const float* __restrict__ bk,
                             const float* __restrict__ lyt_p,
                             const float* __restrict__ cut_p,
                             const float* __restrict__ nit_p)
{
    __shared__ float s_y[M_][NY_];          // staged src_y (18.4 KB)
    __shared__ float s_Wq[3*HD_], s_Wk[3*HD_], s_bq[HD_], s_bk[HD_];
    __shared__ float s_Q[HD_];
    __shared__ float s_ly[M_], s_cu[M_], s_ni[M_], s_scale[M_];
    __shared__ float s_logits[M_][H_];
    __shared__ float s_sm[H_][M_];          // softmax(logits) per head
    __shared__ float s_w[M_];
    __shared__ int   s_map[M_];             // m -> compact slot (or -1)

    const int tid = threadIdx.x;
    const float lyt = *lyt_p;
    const float t_ly = (lyt - 30.0f) / 90.0f;
    const float t_cu = (*cut_p) / 0.0029f;
    const float t_ni = (*nit_p) / 0.0018f;

    // ---- stage everything into shared (coalesced) ----
    for (int p = tid; p < M_ * NY_; p += blockDim.x)
        s_y[p / NY_][p % NY_] = src_y[p];
    if (tid < 3 * HD_) { s_Wq[tid] = Wq[tid]; s_Wk[tid] = Wk[tid]; }
    if (tid < HD_)     { s_bq[tid] = bq[tid]; s_bk[tid] = bk[tid]; }
    if (tid < M_) {
        float lys = params[3*tid + 0];
        s_ly[tid] = (lys - 30.0f) / 90.0f;
        s_cu[tid] = params[3*tid + 1] / 0.0029f;
        s_ni[tid] = params[3*tid + 2] / 0.0018f;
        s_scale[tid] = lyt / lys;
    }
    __syncthreads();

    // ---- Q vector (32 threads) ----
    if (tid < HD_)
        s_Q[tid] = t_ly*s_Wq[tid] + t_cu*s_Wq[HD_+tid] + t_ni*s_Wq[2*HD_+tid] + s_bq[tid];
    __syncthreads();

    // ---- logits (96 threads: one per (m,h)) ----
    if (tid < M_ * H_) {
        int m = tid / H_, h = tid % H_;
        float acc = 0.0f;
        for (int d = 0; d < D_; d++) {
            int k = h*D_ + d;
            float Kv = s_ly[m]*s_Wk[k] + s_cu[m]*s_Wk[HD_+k] + s_ni[m]*s_Wk[2*HD_+k] + s_bk[k];
            acc += Kv * s_Q[k];
        }
        s_logits[m][h] = acc * (1.0f / sqrtf((float)D_));
    }
    __syncthreads();

    // ---- softmax over m, per head (4 threads) ----
    if (tid < H_) {
        int h = tid;
        float mx = -1e30f;
        for (int m = 0; m < M_; m++) mx = fmaxf(mx, s_logits[m][h]);
        float s = 0.0f;
        for (int m = 0; m < M_; m++) s += expf(s_logits[m][h] - mx);
        for (int m = 0; m < M_; m++) s_sm[h][m] = expf(s_logits[m][h] - mx) / s;
    }
    __syncthreads();

    // ---- weights + compaction (serial, tiny) ----
    if (tid == 0) {
        float swv[M_];
        float ssum = 0.0f;
        for (int m = 0; m < M_; m++) {
            float d2 = ((s_ly[m]-t_ly)*(s_ly[m]-t_ly) +
                        (s_cu[m]-t_cu)*(s_cu[m]-t_cu) +
                        (s_ni[m]-t_ni)*(s_ni[m]-t_ni)) / (0.2f*0.2f);
            swv[m] = expf(-d2 * 0.5f);
            ssum += swv[m];
        }
        float wsum = 0.0f;
        for (int m = 0; m < M_; m++) {
            float attn = (s_sm[0][m] + s_sm[1][m] + s_sm[2][m] + s_sm[3][m]) * 0.25f;
            swv[m] = attn * (swv[m] / (ssum + 1e-12f));
            wsum += swv[m];
        }
        int cnt = 0;
        for (int m = 0; m < M_; m++) {
            float w = swv[m] / (wsum + 1e-12f);
            s_w[m] = w;
            s_map[m] = (w >= 1e-6f) ? cnt++ : -1;
        }
        g_mcnt = cnt;
    }
    __syncthreads();

    // ---- x-axis interp setup ----
    if (tid < NG_) {
        float q = (tid == NG_-1) ? 100.0f : (float)tid * (100.0f / 49.0f);
        int lo = 0, hi = NX_;
        while (lo < hi) { int mid = (lo + hi) >> 1; if (gridx(mid) <= q) lo = mid + 1; else hi = mid; }
        int idx = min(max(lo - 1, 0), NX_ - 2);
        float g0 = gridx(idx), g1 = gridx(idx + 1);
        g_ixA[tid] = idx;
        g_fxA[tid] = (q - g0) / (g1 - g0);
        g_mxA[tid] = (q >= 0.0f && q <= 100.0f) ? 1.0f : 0.0f;
    }

    // ---- y-axis tables per (m,j), binary search in SHARED, compact slots ----
    for (int p = tid; p < M_ * NG_; p += blockDim.x) {
        int m = p / NG_, j = p % NG_;
        int slot = s_map[m];
        if (slot < 0) continue;
        float q  = (float)j / 49.0f * lyt;
        float sc = s_scale[m];
        const float* ys = s_y[m];
        int lo = 0, hi = NY_;
        while (lo < hi) { int mid = (lo + hi) >> 1; if (ys[mid]*sc <= q) lo = mid + 1; else hi = mid; }
        int idx = min(max(lo - 1, 0), NY_ - 2);
        float gy0 = ys[idx] * sc, gy1 = ys[idx + 1] * sc;
        float fy = (q - gy0) / (gy1 - gy0);
        float inb = (q >= ys[0]*sc && q <= ys[NY_-1]*sc) ? 1.0f : 0.0f;
        float wm = s_w[m] * inb;
        g_iyA[slot][j] = idx;
        g_e0[slot][j]  = wm * (1.0f - fy);
        g_e1[slot][j]  = wm * fy;
    }

    // ---- time index -> slice offsets (round-half-even), compact slots ----
    for (int p = tid; p < T_ * M_; p += blockDim.x) {
        int t = p / M_, m = p % M_;
        int slot = s_map[m];
        if (slot < 0) continue;
        float tv = (t == T_-1) ? 200.0f : (float)t * (200.0f / 49.0f);
        float r = rintf(tv / stl[m] * (float)(TS_ - 1));
        int ti = min(max((int)r, 0), TS_ - 1);
        g_off[t][slot] = (m * TS_ + ti) * (NX_ * NY_);
    }
}

__global__ __launch_bounds__(256)
void interp_kernel(const float* __restrict__ c1,
                   const float* __restrict__ c2,
                   const float* __restrict__ cut_p,
                   const float* __restrict__ nit_p,
                   float* __restrict__ out)
{
    const int total = 2 * T_ * NG_ * NG_;
    int idx = blockIdx.x * blockDim.x + threadIdx.x;
    if (idx >= total) return;

    int j = idx % NG_;
    int i = (idx / NG_) % NG_;
    int t = (idx / (NG_ * NG_)) % T_;
    int f = idx / (T_ * NG_ * NG_);

    const float* __restrict__ base = f ? c2 : c1;
    const int   ix  = g_ixA[i];
    const float fx  = g_fxA[i];
    const float fx1 = 1.0f - fx;
    const int   cnt = g_mcnt;

    float acc = 0.0f;
#pragma unroll 4
    for (int k = 0; k < cnt; k++) {
        const float* __restrict__ s = base + g_off[t][k] + ix * NY_;
        int iy = g_iyA[k][j];
        float e0 = g_e0[k][j];
        float e1 = g_e1[k][j];
        float v00 = __ldg(s + iy);
        float v01 = __ldg(s + iy + 1);
        float v10 = __ldg(s + NY_ + iy);
        float v11 = __ldg(s + NY_ + iy + 1);
        acc += (v00 * fx1 + v10 * fx) * e0
             + (v01 * fx1 + v11 * fx) * e1;
    }
    float val = acc * g_mxA[i];
    if (f == 0 && j == 0)       val = *cut_p;
    if (f == 1 && j == NG_ - 1) val = *nit_p;
    out[idx] = val;
}

extern "C" void kernel_launch(void* const* d_in, const int* in_sizes, int n_in,
                              void* d_out, int out_size)
{
    const float* c1    = (const float*)d_in[0];
    const float* c2    = (const float*)d_in[1];
    const float* params= (const float*)d_in[2];
    const float* src_y = (const float*)d_in[3];
    const float* stl   = (const float*)d_in[4];
    const float* Wq    = (const float*)d_in[5];
    const float* bq    = (const float*)d_in[6];
    const float* Wk    = (const float*)d_in[7];
    const float* bk    = (const float*)d_in[8];
    const float* lyt   = (const float*)d_in[9];
    const float* cut   = (const float*)d_in[10];
    const float* nit   = (const float*)d_in[11];
    float* out = (float*)d_out;

    setup_kernel<<<1, 256>>>(params, src_y, stl, Wq, bq, Wk, bk, lyt, cut, nit);

    const int total = 2 * T_ * NG_ * NG_;
    interp_kernel<<<(total + 255) / 256, 256>>>(c1, c2, cut, nit, out);
}